// round 9
// baseline (speedup 1.0000x reference)
#include <cuda_runtime.h>
#include <cuda_fp16.h>

#define H 128
#define HH (H * H)
#define TILE_N 64
#define NTG 128       // GEMM block threads
#define NT 256
#define MAXN 50176
#define MAXE 800000
#define SCAN_BLK 256

typedef unsigned long long ull;

// Scratch (device globals — no allocation allowed)
__device__ float  g_h0[(size_t)MAXN * H];
__device__ float  g_agg[(size_t)MAXN * H];      // normalized neighbor mean
__device__ float  g_x1[(size_t)MAXN * H];
__device__ float  g_partial[(size_t)MAXN * H];  // self-GEMM raw sums
__device__ __half g_h0h[(size_t)MAXN * H];      // fp16 shadow of h0
__device__ __half g_x1h[(size_t)MAXN * H];      // fp16 shadow of x1
__device__ float  g_wt[5 * HH];                 // transposed weights: [k][j]
__device__ int    g_cnt[MAXN];
__device__ int    g_off[MAXN + 1];
__device__ int    g_csr[MAXE];
__device__ int    g_bsum[(MAXN + SCAN_BLK - 1) / SCAN_BLK];

// ---------------------------------------------------------------------------
// f32x2 helpers
// ---------------------------------------------------------------------------
__device__ __forceinline__ ull splat2(float x) {
    ull d;
    asm("mov.b64 %0, {%1, %1};" : "=l"(d) : "f"(x));
    return d;
}
__device__ __forceinline__ void fma2(ull& acc, ull a, ull b) {
    asm("fma.rn.f32x2 %0, %1, %2, %0;" : "+l"(acc) : "l"(a), "l"(b));
}
__device__ __forceinline__ void unpack2(ull v, float& lo, float& hi) {
    asm("mov.b64 {%0, %1}, %2;" : "=f"(lo), "=f"(hi) : "l"(v));
}

// half helpers: pack 4 floats -> 4 halves (8 bytes)
__device__ __forceinline__ uint2 pack4h(float a, float b, float c, float d) {
    uint2 r;
    __half2 h0 = __float22half2_rn(make_float2(a, b));
    __half2 h1 = __float22half2_rn(make_float2(c, d));
    r.x = *(unsigned*)&h0;
    r.y = *(unsigned*)&h1;
    return r;
}

// ---------------------------------------------------------------------------
// Transpose all five W[j][k] into g_wt slots as Wt[k][j]; slot 0 zeroes g_cnt.
// ---------------------------------------------------------------------------
__global__ void transpose_w_all(const float* __restrict__ W0,
                                const float* __restrict__ W1,
                                const float* __restrict__ W2,
                                const float* __restrict__ W3,
                                const float* __restrict__ W4, int N) {
    int slot = blockIdx.y;
    const float* W = (slot == 0) ? W0 : (slot == 1) ? W1 : (slot == 2) ? W2
                   : (slot == 3) ? W3 : W4;
    int idx = blockIdx.x * blockDim.x + threadIdx.x;
    if (idx < HH) {
        int j = idx >> 7;
        int k = idx & 127;
        g_wt[slot * HH + k * H + j] = W[idx];
    }
    if (slot == 0) {
        for (int i = idx; i < N; i += gridDim.x * blockDim.x) g_cnt[i] = 0;
    }
}

// ---------------------------------------------------------------------------
// CSR build kernels
// ---------------------------------------------------------------------------
__global__ void deg_hist(const int* __restrict__ ei, int E) {
    int e = blockIdx.x * blockDim.x + threadIdx.x;
    if (e < E) atomicAdd(&g_cnt[ei[E + e]], 1);
}

__global__ void scanA(int N) {
    __shared__ int sh[SCAN_BLK];
    int tid = threadIdx.x;
    int gi = blockIdx.x * SCAN_BLK + tid;
    int v = (gi < N) ? g_cnt[gi] : 0;
    sh[tid] = v;
    __syncthreads();
#pragma unroll
    for (int off = 1; off < SCAN_BLK; off <<= 1) {
        int t = (tid >= off) ? sh[tid - off] : 0;
        __syncthreads();
        sh[tid] += t;
        __syncthreads();
    }
    if (gi < N) g_off[gi] = sh[tid] - v;
    if (tid == SCAN_BLK - 1) g_bsum[blockIdx.x] = sh[tid];
}

__global__ void scanC(int N, int E, int nblk) {
    __shared__ int sh[SCAN_BLK];
    __shared__ int ex[SCAN_BLK];
    int tid = threadIdx.x;
    int v = (tid < nblk) ? g_bsum[tid] : 0;
    sh[tid] = v;
    __syncthreads();
#pragma unroll
    for (int off = 1; off < SCAN_BLK; off <<= 1) {
        int t = (tid >= off) ? sh[tid - off] : 0;
        __syncthreads();
        sh[tid] += t;
        __syncthreads();
    }
    ex[tid] = sh[tid] - v;
    __syncthreads();
    int add = ex[blockIdx.x];
    int gi = blockIdx.x * SCAN_BLK + tid;
    if (gi < N) g_off[gi] += add;
    if (blockIdx.x == 0 && tid == 0) g_off[N] = E;
}

__global__ void csr_fill(const int* __restrict__ ei, int E) {
    int e = blockIdx.x * blockDim.x + threadIdx.x;
    if (e >= E) return;
    int s = ei[e];
    int t = ei[E + e];
    int pos = atomicAdd(&g_cnt[t], -1) - 1;
    g_csr[g_off[t] + pos] = s;
}

// ---------------------------------------------------------------------------
// Register-tiled accumulate with FFMA2: 8 nodes x 8 outputs per thread.
// ---------------------------------------------------------------------------
__device__ __forceinline__ void mm_accum8(const float* __restrict__ Xs,
                                          const float* __restrict__ Ws,
                                          int n0, int jlo, ull acc[8][4]) {
#pragma unroll
    for (int k4 = 0; k4 < H; k4 += 4) {
        float4 xv[8];
#pragma unroll
        for (int i = 0; i < 8; i++)
            xv[i] = *(const float4*)(Xs + (n0 + i) * H + k4);
#pragma unroll
        for (int kk = 0; kk < 4; kk++) {
            const int k = k4 + kk;
            ulonglong2 wa = *(const ulonglong2*)(Ws + k * H + jlo);
            ulonglong2 wb = *(const ulonglong2*)(Ws + k * H + jlo + 64);
#pragma unroll
            for (int i = 0; i < 8; i++) {
                float xs = (kk == 0) ? xv[i].x : (kk == 1) ? xv[i].y
                         : (kk == 2) ? xv[i].z : xv[i].w;
                ull x2 = splat2(xs);
                fma2(acc[i][0], x2, wa.x);
                fma2(acc[i][1], x2, wa.y);
                fma2(acc[i][2], x2, wb.x);
                fma2(acc[i][3], x2, wb.y);
            }
        }
    }
}

// ---------------------------------------------------------------------------
// Aggregation (fp16 rows): ONE WARP PER NODE, divergence-free.
// Lanes 0-15 process even-indexed edges, lanes 16-31 odd-indexed (one LDG.128
// covers 2 rows). fp32 accumulate; cross-half combine via shfl_xor(16).
// ---------------------------------------------------------------------------
__device__ __forceinline__ void hacc(float2& a0, float2& a1, float2& a2,
                                     float2& a3, uint4 v) {
    __half2* p = (__half2*)&v;
    float2 f0 = __half22float2(p[0]);
    float2 f1 = __half22float2(p[1]);
    float2 f2 = __half22float2(p[2]);
    float2 f3 = __half22float2(p[3]);
    a0.x += f0.x; a0.y += f0.y;
    a1.x += f1.x; a1.y += f1.y;
    a2.x += f2.x; a2.y += f2.y;
    a3.x += f3.x; a3.y += f3.y;
}

__global__ void gather_agg_h(int xsel, int N) {
    int gt = blockIdx.x * blockDim.x + threadIdx.x;
    int node = gt >> 5;
    if (node >= N) return;
    const int lane = gt & 31;
    const int half = lane >> 4;          // 0: even edges, 1: odd edges
    const int l = lane & 15;
    const __half* __restrict__ h = xsel ? g_x1h : g_h0h;
    const int col = l << 3;              // 8 halves (16B) per lane

    int beg = g_off[node];
    int end = g_off[node + 1];
    float2 a0 = {0.f, 0.f}, a1 = {0.f, 0.f}, a2 = {0.f, 0.f}, a3 = {0.f, 0.f};

    int i = beg;
    // unrolled: 4 edges per iteration (2 per half), fully uniform
    for (; i + 4 <= end; i += 4) {
        int sA = __ldg(&g_csr[i + half]);
        int sB = __ldg(&g_csr[i + 2 + half]);
        uint4 vA = *(const uint4*)(h + (size_t)sA * H + col);
        uint4 vB = *(const uint4*)(h + (size_t)sB * H + col);
        hacc(a0, a1, a2, a3, vA);
        hacc(a0, a1, a2, a3, vB);
    }
    // remainder (0-3 edges), uniform loop with predicated load
    for (; i < end; i += 2) {
        int idx = i + half;
        if (idx < end) {
            int s = __ldg(&g_csr[idx]);
            uint4 v = *(const uint4*)(h + (size_t)s * H + col);
            hacc(a0, a1, a2, a3, v);
        }
    }

    // combine halves: lane l += lane l+16
    a0.x += __shfl_xor_sync(0xffffffffu, a0.x, 16);
    a0.y += __shfl_xor_sync(0xffffffffu, a0.y, 16);
    a1.x += __shfl_xor_sync(0xffffffffu, a1.x, 16);
    a1.y += __shfl_xor_sync(0xffffffffu, a1.y, 16);
    a2.x += __shfl_xor_sync(0xffffffffu, a2.x, 16);
    a2.y += __shfl_xor_sync(0xffffffffu, a2.y, 16);
    a3.x += __shfl_xor_sync(0xffffffffu, a3.x, 16);
    a3.y += __shfl_xor_sync(0xffffffffu, a3.y, 16);

    if (half == 0) {
        float inv = 1.0f / (float)max(end - beg, 1);
        float4 r1 = make_float4(a0.x * inv, a0.y * inv, a1.x * inv, a1.y * inv);
        float4 r2 = make_float4(a2.x * inv, a2.y * inv, a3.x * inv, a3.y * inv);
        *(float4*)(g_agg + (size_t)node * H + col) = r1;
        *(float4*)(g_agg + (size_t)node * H + col + 4) = r2;
    }
}

// ---------------------------------------------------------------------------
// Input layer: h0 = relu( concat(attr,cc,bl,exist) @ W_in^T + b_in )
// Writes fp32 g_h0 and fp16 g_h0h.
// ---------------------------------------------------------------------------
__global__ void __launch_bounds__(NTG, 2)
input_gemm(const float* __restrict__ attr, int ATTR,
           const float* __restrict__ cc,
           const float* __restrict__ bl,
           const float* __restrict__ exist,
           const float* __restrict__ b, int N) {
    extern __shared__ float sm[];
    float* Xs = sm;              // TILE_N * H
    float* Ws = sm + TILE_N * H; // HH
    const int tid = threadIdx.x;
    const int nb = blockIdx.x * TILE_N;

    for (int idx = tid; idx < HH / 4; idx += NTG)
        ((float4*)Ws)[idx] = ((const float4*)g_wt)[idx];  // slot 0

    for (int idx = tid; idx < TILE_N * H; idx += NTG) {
        int n = idx >> 7, k = idx & 127;
        int gn = nb + n;
        float v = 0.f;
        if (gn < N) {
            if (k < ATTR)            v = attr[(size_t)gn * ATTR + k];
            else if (k == ATTR)      v = cc[gn];
            else if (k == ATTR + 1)  v = bl[gn];
            else if (k == ATTR + 2)  v = exist[gn];
        }
        Xs[idx] = v;
    }
    __syncthreads();

    const int jt = tid & 15, nt = tid >> 4;
    const int jlo = jt * 4, n0 = nt * 8;
    ull acc[8][4] = {};
    mm_accum8(Xs, Ws, n0, jlo, acc);

#pragma unroll
    for (int i = 0; i < 8; i++) {
        int gn = nb + n0 + i;
        if (gn >= N) continue;
        float o[8];
        unpack2(acc[i][0], o[0], o[1]);
        unpack2(acc[i][1], o[2], o[3]);
        unpack2(acc[i][2], o[4], o[5]);
        unpack2(acc[i][3], o[6], o[7]);
        float4 o1, o2;
        o1.x = fmaxf(o[0] + b[jlo + 0], 0.f);
        o1.y = fmaxf(o[1] + b[jlo + 1], 0.f);
        o1.z = fmaxf(o[2] + b[jlo + 2], 0.f);
        o1.w = fmaxf(o[3] + b[jlo + 3], 0.f);
        o2.x = fmaxf(o[4] + b[jlo + 64], 0.f);
        o2.y = fmaxf(o[5] + b[jlo + 65], 0.f);
        o2.z = fmaxf(o[6] + b[jlo + 66], 0.f);
        o2.w = fmaxf(o[7] + b[jlo + 67], 0.f);
        *(float4*)(g_h0 + (size_t)gn * H + jlo) = o1;
        *(float4*)(g_h0 + (size_t)gn * H + jlo + 64) = o2;
        *(uint2*)(g_h0h + (size_t)gn * H + jlo) = pack4h(o1.x, o1.y, o1.z, o1.w);
        *(uint2*)(g_h0h + (size_t)gn * H + jlo + 64) = pack4h(o2.x, o2.y, o2.z, o2.w);
    }
}

// ---------------------------------------------------------------------------
// Self-GEMM: g_partial = X @ Ws^T (raw sums, no bias)
// ---------------------------------------------------------------------------
__global__ void __launch_bounds__(NTG, 2)
self_gemm(int xsel, int wslot_self, int N) {
    extern __shared__ float sm[];
    float* Xs = sm;
    float* Ws = sm + TILE_N * H;
    const int tid = threadIdx.x;
    const int nb = blockIdx.x * TILE_N;
    const int jt = tid & 15, nt = tid >> 4;
    const int jlo = jt * 4, n0 = nt * 8;
    const float* __restrict__ X = xsel ? g_x1 : g_h0;

    for (int idx = tid; idx < HH / 4; idx += NTG)
        ((float4*)Ws)[idx] = ((const float4*)(g_wt + wslot_self * HH))[idx];
    for (int idx = tid; idx < TILE_N * (H / 4); idx += NTG) {
        int n = idx >> 5, kq = idx & 31;
        int gn = nb + n;
        float4 v = make_float4(0.f, 0.f, 0.f, 0.f);
        if (gn < N) v = *(const float4*)(X + (size_t)gn * H + kq * 4);
        *(float4*)(Xs + n * H + kq * 4) = v;
    }
    __syncthreads();

    ull acc[8][4] = {};
    mm_accum8(Xs, Ws, n0, jlo, acc);

#pragma unroll
    for (int i = 0; i < 8; i++) {
        int gn = nb + n0 + i;
        if (gn >= N) continue;
        float o[8];
        unpack2(acc[i][0], o[0], o[1]);
        unpack2(acc[i][1], o[2], o[3]);
        unpack2(acc[i][2], o[4], o[5]);
        unpack2(acc[i][3], o[6], o[7]);
        *(float4*)(g_partial + (size_t)gn * H + jlo) = make_float4(o[0], o[1], o[2], o[3]);
        *(float4*)(g_partial + (size_t)gn * H + jlo + 64) = make_float4(o[4], o[5], o[6], o[7]);
    }
}

// ---------------------------------------------------------------------------
// sageB: neigh-GEMM over g_agg + epilogue (partial + biases, relu, exist).
// Layer 1 (out==nullptr): writes g_x1 fp32 + g_x1h fp16.
// ---------------------------------------------------------------------------
__global__ void __launch_bounds__(NTG, 2)
sageB(int wslot_neigh,
      const float* __restrict__ bs,
      const float* __restrict__ bn,
      const float* __restrict__ exist,
      float* out, int N, int do_relu) {
    extern __shared__ float sm[];
    float* Xs = sm;
    float* Ws = sm + TILE_N * H;
    const int tid = threadIdx.x;
    const int nb = blockIdx.x * TILE_N;
    const int jt = tid & 15, nt = tid >> 4;
    const int jlo = jt * 4, n0 = nt * 8;
    float* dst = out ? out : g_x1;
    const bool write_h = (out == nullptr);

    for (int idx = tid; idx < HH / 4; idx += NTG)
        ((float4*)Ws)[idx] = ((const float4*)(g_wt + wslot_neigh * HH))[idx];
    for (int idx = tid; idx < TILE_N * (H / 4); idx += NTG) {
        int n = idx >> 5, kq = idx & 31;
        int gn = nb + n;
        float4 v = make_float4(0.f, 0.f, 0.f, 0.f);
        if (gn < N) v = *(const float4*)(g_agg + (size_t)gn * H + kq * 4);
        *(float4*)(Xs + n * H + kq * 4) = v;
    }
    __syncthreads();

    ull acc[8][4] = {};
    mm_accum8(Xs, Ws, n0, jlo, acc);

#pragma unroll
    for (int i = 0; i < 8; i++) {
        int gn = nb + n0 + i;
        if (gn >= N) continue;
        float ex = exist[gn];
        float o[8];
        unpack2(acc[i][0], o[0], o[1]);
        unpack2(acc[i][1], o[2], o[3]);
        unpack2(acc[i][2], o[4], o[5]);
        unpack2(acc[i][3], o[6], o[7]);
        float4 p1 = *(const float4*)(g_partial + (size_t)gn * H + jlo);
        float4 p2 = *(const float4*)(g_partial + (size_t)gn * H + jlo + 64);
        float pa[8] = {p1.x, p1.y, p1.z, p1.w, p2.x, p2.y, p2.z, p2.w};
        float r[8];
#pragma unroll
        for (int q = 0; q < 4; q++) {
            float v1 = o[q] + pa[q] + bs[jlo + q] + bn[jlo + q];
            float v2 = o[q + 4] + pa[q + 4] + bs[jlo + 64 + q] + bn[jlo + 64 + q];
            if (do_relu) { v1 = fmaxf(v1, 0.f); v2 = fmaxf(v2, 0.f); }
            r[q] = v1 * ex;
            r[q + 4] = v2 * ex;
        }
        *(float4*)(dst + (size_t)gn * H + jlo) = make_float4(r[0], r[1], r[2], r[3]);
        *(float4*)(dst + (size_t)gn * H + jlo + 64) = make_float4(r[4], r[5], r[6], r[7]);
        if (write_h) {
            *(uint2*)(g_x1h + (size_t)gn * H + jlo) = pack4h(r[0], r[1], r[2], r[3]);
            *(uint2*)(g_x1h + (size_t)gn * H + jlo + 64) = pack4h(r[4], r[5], r[6], r[7]);
        }
    }
}

// ---------------------------------------------------------------------------
extern "C" void kernel_launch(void* const* d_in, const int* in_sizes, int n_in,
                              void* d_out, int out_size) {
    const float* attr  = (const float*)d_in[0];
    const float* cc    = (const float*)d_in[1];
    const float* bl    = (const float*)d_in[2];
    const float* exist = (const float*)d_in[3];
    const float* W_in  = (const float*)d_in[4];
    const float* b_in  = (const float*)d_in[5];
    const float* W1s   = (const float*)d_in[6];
    const float* b1s   = (const float*)d_in[7];
    const float* W1n   = (const float*)d_in[8];
    const float* b1n   = (const float*)d_in[9];
    const float* W2s   = (const float*)d_in[10];
    const float* b2s   = (const float*)d_in[11];
    const float* W2n   = (const float*)d_in[12];
    const float* b2n   = (const float*)d_in[13];
    const int*   ei    = (const int*)d_in[14];   // int32 (JAX x64 disabled)

    const int N    = in_sizes[3];
    const int ATTR = in_sizes[0] / N;
    const int E    = in_sizes[14] / 2;
    float* out = (float*)d_out;

    static cudaStream_t s1 = nullptr;
    static cudaEvent_t evT, evCSR, evIn, evS1, evX1, evS2;
    if (!s1) {
        cudaStreamCreateWithFlags(&s1, cudaStreamNonBlocking);
        cudaEventCreateWithFlags(&evT,   cudaEventDisableTiming);
        cudaEventCreateWithFlags(&evCSR, cudaEventDisableTiming);
        cudaEventCreateWithFlags(&evIn,  cudaEventDisableTiming);
        cudaEventCreateWithFlags(&evS1,  cudaEventDisableTiming);
        cudaEventCreateWithFlags(&evX1,  cudaEventDisableTiming);
        cudaEventCreateWithFlags(&evS2,  cudaEventDisableTiming);
    }

    const int SMEM = (TILE_N * H + HH) * (int)sizeof(float);
    cudaFuncSetAttribute(input_gemm, cudaFuncAttributeMaxDynamicSharedMemorySize, SMEM);
    cudaFuncSetAttribute(self_gemm,  cudaFuncAttributeMaxDynamicSharedMemorySize, SMEM);
    cudaFuncSetAttribute(sageB,      cudaFuncAttributeMaxDynamicSharedMemorySize, SMEM);

    const int G = (N + TILE_N - 1) / TILE_N;
    const int edge_grid = (E + NT - 1) / NT;
    const int scan_grid = (N + SCAN_BLK - 1) / SCAN_BLK;
    const long long ga_threads = (long long)N * 32;     // warp per node
    const int ga_grid = (int)((ga_threads + NT - 1) / NT);
    cudaStream_t ms = (cudaStream_t)0;  // main (capturing) stream

    // main: weight transposes + zero g_cnt
    dim3 tr_grid((HH + NT - 1) / NT, 5);
    transpose_w_all<<<tr_grid, NT, 0, ms>>>(W_in, W1s, W1n, W2s, W2n, N);
    cudaEventRecord(evT, ms);

    // s1: CSR build chain
    cudaStreamWaitEvent(s1, evT, 0);
    deg_hist<<<edge_grid, NT, 0, s1>>>(ei, E);
    scanA<<<scan_grid, SCAN_BLK, 0, s1>>>(N);
    scanC<<<scan_grid, SCAN_BLK, 0, s1>>>(N, E, scan_grid);
    csr_fill<<<edge_grid, NT, 0, s1>>>(ei, E);
    cudaEventRecord(evCSR, s1);

    // main: input GEMM overlaps CSR build
    input_gemm<<<G, NTG, SMEM, ms>>>(attr, ATTR, cc, bl, exist, b_in, N);
    cudaEventRecord(evIn, ms);

    // ----- layer 1: self-GEMM (s1) || gather (main) -----
    cudaStreamWaitEvent(s1, evIn, 0);
    self_gemm<<<G, NTG, SMEM, s1>>>(0, 1, N);
    cudaEventRecord(evS1, s1);

    cudaStreamWaitEvent(ms, evCSR, 0);
    gather_agg_h<<<ga_grid, NT, 0, ms>>>(0, N);
    cudaStreamWaitEvent(ms, evS1, 0);
    sageB<<<G, NTG, SMEM, ms>>>(2, b1s, b1n, exist, nullptr, N, 1);
    cudaEventRecord(evX1, ms);

    // ----- layer 2: self-GEMM (s1) || gather (main) -----
    cudaStreamWaitEvent(s1, evX1, 0);
    self_gemm<<<G, NTG, SMEM, s1>>>(1, 3, N);
    cudaEventRecord(evS2, s1);

    gather_agg_h<<<ga_grid, NT, 0, ms>>>(1, N);
    cudaStreamWaitEvent(ms, evS2, 0);
    sageB<<<G, NTG, SMEM, ms>>>(4, b2s, b2n, exist, out, N, 0);
}

// round 10
// speedup vs baseline: 2.3324x; 2.3324x over previous
#include <cuda_runtime.h>
#include <cuda_fp16.h>

#define H 128
#define HH (H * H)
#define TILE_M 64
#define NTG 256       // GEMM block threads (8 warps)
#define NT 256
#define MAXN 50176
#define MAXE 800000
#define SCAN_BLK 256
#define XPAD 136      // smem row pitch in halves (128 + 8, conflict-free frags)

typedef unsigned long long ull;

// Scratch (device globals — no allocation allowed)
__device__ float  g_partial[(size_t)MAXN * H];  // self-GEMM raw sums
__device__ __half g_h0h[(size_t)MAXN * H];      // layer-0 activations (fp16)
__device__ __half g_x1h[(size_t)MAXN * H];      // layer-1 activations (fp16)
__device__ __half g_aggh[(size_t)MAXN * H];     // neighbor mean (fp16)
__device__ __half g_wh[5 * HH];                 // fp16 weights, native [j][k]
__device__ int    g_cnt[MAXN];
__device__ int    g_off[MAXN + 1];
__device__ int    g_csr[MAXE];
__device__ int    g_bsum[(MAXN + SCAN_BLK - 1) / SCAN_BLK];

// half helpers
__device__ __forceinline__ uint2 pack4h(float a, float b, float c, float d) {
    uint2 r;
    __half2 h0 = __float22half2_rn(make_float2(a, b));
    __half2 h1 = __float22half2_rn(make_float2(c, d));
    r.x = *(unsigned*)&h0;
    r.y = *(unsigned*)&h1;
    return r;
}

// ---------------------------------------------------------------------------
// Prep: convert five W [H,H] fp32 -> fp16 (native layout); slot 0 zeroes g_cnt
// ---------------------------------------------------------------------------
__global__ void prep_weights(const float* __restrict__ W0,
                             const float* __restrict__ W1,
                             const float* __restrict__ W2,
                             const float* __restrict__ W3,
                             const float* __restrict__ W4, int N) {
    int slot = blockIdx.y;
    const float* W = (slot == 0) ? W0 : (slot == 1) ? W1 : (slot == 2) ? W2
                   : (slot == 3) ? W3 : W4;
    int idx = blockIdx.x * blockDim.x + threadIdx.x;
    if (idx < HH) g_wh[slot * HH + idx] = __float2half(W[idx]);
    if (slot == 0) {
        for (int i = idx; i < N; i += gridDim.x * blockDim.x) g_cnt[i] = 0;
    }
}

// ---------------------------------------------------------------------------
// CSR build kernels
// ---------------------------------------------------------------------------
__global__ void deg_hist(const int* __restrict__ ei, int E) {
    int e = blockIdx.x * blockDim.x + threadIdx.x;
    if (e < E) atomicAdd(&g_cnt[ei[E + e]], 1);
}

__global__ void scanA(int N) {
    __shared__ int sh[SCAN_BLK];
    int tid = threadIdx.x;
    int gi = blockIdx.x * SCAN_BLK + tid;
    int v = (gi < N) ? g_cnt[gi] : 0;
    sh[tid] = v;
    __syncthreads();
#pragma unroll
    for (int off = 1; off < SCAN_BLK; off <<= 1) {
        int t = (tid >= off) ? sh[tid - off] : 0;
        __syncthreads();
        sh[tid] += t;
        __syncthreads();
    }
    if (gi < N) g_off[gi] = sh[tid] - v;
    if (tid == SCAN_BLK - 1) g_bsum[blockIdx.x] = sh[tid];
}

__global__ void scanC(int N, int E, int nblk) {
    __shared__ int sh[SCAN_BLK];
    __shared__ int ex[SCAN_BLK];
    int tid = threadIdx.x;
    int v = (tid < nblk) ? g_bsum[tid] : 0;
    sh[tid] = v;
    __syncthreads();
#pragma unroll
    for (int off = 1; off < SCAN_BLK; off <<= 1) {
        int t = (tid >= off) ? sh[tid - off] : 0;
        __syncthreads();
        sh[tid] += t;
        __syncthreads();
    }
    ex[tid] = sh[tid] - v;
    __syncthreads();
    int add = ex[blockIdx.x];
    int gi = blockIdx.x * SCAN_BLK + tid;
    if (gi < N) g_off[gi] += add;
    if (blockIdx.x == 0 && tid == 0) g_off[N] = E;
}

__global__ void csr_fill(const int* __restrict__ ei, int E) {
    int e = blockIdx.x * blockDim.x + threadIdx.x;
    if (e >= E) return;
    int s = ei[e];
    int t = ei[E + e];
    int pos = atomicAdd(&g_cnt[t], -1) - 1;
    g_csr[g_off[t] + pos] = s;
}

// ---------------------------------------------------------------------------
// Gather (fp16 rows): one warp per node; lanes 0-15 even edges, 16-31 odd.
// fp32 accumulate, shfl-combine, write fp16 mean to g_aggh.
// ---------------------------------------------------------------------------
__device__ __forceinline__ void hacc(float2& a0, float2& a1, float2& a2,
                                     float2& a3, uint4 v) {
    __half2* p = (__half2*)&v;
    float2 f0 = __half22float2(p[0]);
    float2 f1 = __half22float2(p[1]);
    float2 f2 = __half22float2(p[2]);
    float2 f3 = __half22float2(p[3]);
    a0.x += f0.x; a0.y += f0.y;
    a1.x += f1.x; a1.y += f1.y;
    a2.x += f2.x; a2.y += f2.y;
    a3.x += f3.x; a3.y += f3.y;
}

__global__ void gather_agg_h(int xsel, int N) {
    int gt = blockIdx.x * blockDim.x + threadIdx.x;
    int node = gt >> 5;
    if (node >= N) return;
    const int lane = gt & 31;
    const int half = lane >> 4;
    const int l = lane & 15;
    const __half* __restrict__ h = xsel ? g_x1h : g_h0h;
    const int col = l << 3;

    int beg = g_off[node];
    int end = g_off[node + 1];
    float2 a0 = {0.f, 0.f}, a1 = {0.f, 0.f}, a2 = {0.f, 0.f}, a3 = {0.f, 0.f};

    int i = beg;
    for (; i + 4 <= end; i += 4) {
        int sA = __ldg(&g_csr[i + half]);
        int sB = __ldg(&g_csr[i + 2 + half]);
        uint4 vA = *(const uint4*)(h + (size_t)sA * H + col);
        uint4 vB = *(const uint4*)(h + (size_t)sB * H + col);
        hacc(a0, a1, a2, a3, vA);
        hacc(a0, a1, a2, a3, vB);
    }
    for (; i < end; i += 2) {
        int idx = i + half;
        if (idx < end) {
            int s = __ldg(&g_csr[idx]);
            uint4 v = *(const uint4*)(h + (size_t)s * H + col);
            hacc(a0, a1, a2, a3, v);
        }
    }

    a0.x += __shfl_xor_sync(0xffffffffu, a0.x, 16);
    a0.y += __shfl_xor_sync(0xffffffffu, a0.y, 16);
    a1.x += __shfl_xor_sync(0xffffffffu, a1.x, 16);
    a1.y += __shfl_xor_sync(0xffffffffu, a1.y, 16);
    a2.x += __shfl_xor_sync(0xffffffffu, a2.x, 16);
    a2.y += __shfl_xor_sync(0xffffffffu, a2.y, 16);
    a3.x += __shfl_xor_sync(0xffffffffu, a3.x, 16);
    a3.y += __shfl_xor_sync(0xffffffffu, a3.y, 16);

    if (half == 0) {
        float inv = 1.0f / (float)max(end - beg, 1);
        uint4 o;
        uint2 lo = pack4h(a0.x * inv, a0.y * inv, a1.x * inv, a1.y * inv);
        uint2 hi = pack4h(a2.x * inv, a2.y * inv, a3.x * inv, a3.y * inv);
        o.x = lo.x; o.y = lo.y; o.z = hi.x; o.w = hi.y;
        *(uint4*)(g_aggh + (size_t)node * H + col) = o;
    }
}

// ---------------------------------------------------------------------------
// HMMA warp GEMM core: one warp computes m16 x n64 (8 n-tiles) over K=128.
// A from Xs [TILE_M][XPAD] halves (row-major m,k); B from Wsm [128][XPAD]
// (native [n][k] = col-major k,n for mma row.col). Direct LDS.b32 fragments.
// ---------------------------------------------------------------------------
__device__ __forceinline__ void warp_mma(const __half* __restrict__ Xs,
                                         const __half* __restrict__ Wsm,
                                         int m0, int nbase, int lane,
                                         float c[8][4]) {
    const int g = lane >> 2, tig = lane & 3;
    const __half* arow0 = Xs + (m0 + g) * XPAD + tig * 2;
    const __half* arow8 = Xs + (m0 + g + 8) * XPAD + tig * 2;
#pragma unroll
    for (int kc = 0; kc < 8; kc++) {
        unsigned a0 = *(const unsigned*)(arow0 + kc * 16);
        unsigned a1 = *(const unsigned*)(arow8 + kc * 16);
        unsigned a2 = *(const unsigned*)(arow0 + kc * 16 + 8);
        unsigned a3 = *(const unsigned*)(arow8 + kc * 16 + 8);
#pragma unroll
        for (int nt = 0; nt < 8; nt++) {
            const __half* brow = Wsm + (nbase + nt * 8 + g) * XPAD + kc * 16 + tig * 2;
            unsigned b0 = *(const unsigned*)(brow);
            unsigned b1 = *(const unsigned*)(brow + 8);
            asm volatile(
                "mma.sync.aligned.m16n8k16.row.col.f32.f16.f16.f32 "
                "{%0,%1,%2,%3}, {%4,%5,%6,%7}, {%8,%9}, {%0,%1,%2,%3};"
                : "+f"(c[nt][0]), "+f"(c[nt][1]), "+f"(c[nt][2]), "+f"(c[nt][3])
                : "r"(a0), "r"(a1), "r"(a2), "r"(a3), "r"(b0), "r"(b1));
        }
    }
}

// load W slot into smem [128][XPAD]
__device__ __forceinline__ void fill_w(__half* Wsm, int slot, int tid) {
    const __half* src = g_wh + slot * HH;
    for (int idx = tid; idx < 128 * 16; idx += NTG) {
        int r = idx >> 4, ch = idx & 15;
        *(uint4*)(Wsm + r * XPAD + ch * 8) = *(const uint4*)(src + r * H + ch * 8);
    }
}

// load fp16 activation tile into smem [TILE_M][XPAD]
__device__ __forceinline__ void fill_x(__half* Xs, const __half* src,
                                       int nb, int N, int tid) {
    for (int idx = tid; idx < TILE_M * 16; idx += NTG) {
        int r = idx >> 4, ch = idx & 15;
        int gr = nb + r;
        uint4 v = make_uint4(0, 0, 0, 0);
        if (gr < N) v = *(const uint4*)(src + (size_t)gr * H + ch * 8);
        *(uint4*)(Xs + r * XPAD + ch * 8) = v;
    }
}

// ---------------------------------------------------------------------------
// Input layer: h0h = fp16(relu(concat(attr,cc,bl,exist) @ W_in^T + b_in))
// ---------------------------------------------------------------------------
__global__ void __launch_bounds__(NTG)
input_gemm(const float* __restrict__ attr, int ATTR,
           const float* __restrict__ cc,
           const float* __restrict__ bl,
           const float* __restrict__ exist,
           const float* __restrict__ b, int N) {
    extern __shared__ __half sm[];
    __half* Xs = sm;                       // TILE_M * XPAD
    __half* Wsm = sm + TILE_M * XPAD;      // 128 * XPAD
    const int tid = threadIdx.x;
    const int nb = blockIdx.x * TILE_M;

    fill_w(Wsm, 0, tid);
    for (int idx = tid; idx < TILE_M * H; idx += NTG) {
        int n = idx >> 7, k = idx & 127;
        int gn = nb + n;
        float v = 0.f;
        if (gn < N) {
            if (k < ATTR)            v = attr[(size_t)gn * ATTR + k];
            else if (k == ATTR)      v = cc[gn];
            else if (k == ATTR + 1)  v = bl[gn];
            else if (k == ATTR + 2)  v = exist[gn];
        }
        Xs[n * XPAD + k] = __float2half(v);
    }
    __syncthreads();

    const int wid = tid >> 5, lane = tid & 31;
    const int m0 = (wid & 3) * 16, nbase = (wid >> 2) * 64;
    const int g = lane >> 2, tig = lane & 3;
    float c[8][4] = {};
    warp_mma(Xs, Wsm, m0, nbase, lane, c);

    int r0 = nb + m0 + g, r1 = r0 + 8;
#pragma unroll
    for (int nt = 0; nt < 8; nt++) {
        int col = nbase + nt * 8 + tig * 2;
        float b0 = b[col], b1 = b[col + 1];
        if (r0 < N) {
            float v0 = fmaxf(c[nt][0] + b0, 0.f);
            float v1 = fmaxf(c[nt][1] + b1, 0.f);
            __half2 hv = __float22half2_rn(make_float2(v0, v1));
            *(unsigned*)(g_h0h + (size_t)r0 * H + col) = *(unsigned*)&hv;
        }
        if (r1 < N) {
            float v0 = fmaxf(c[nt][2] + b0, 0.f);
            float v1 = fmaxf(c[nt][3] + b1, 0.f);
            __half2 hv = __float22half2_rn(make_float2(v0, v1));
            *(unsigned*)(g_h0h + (size_t)r1 * H + col) = *(unsigned*)&hv;
        }
    }
}

// ---------------------------------------------------------------------------
// Self-GEMM: g_partial = X(fp16) @ Ws^T  (raw fp32 sums)
// ---------------------------------------------------------------------------
__global__ void __launch_bounds__(NTG)
self_gemm(int xsel, int wslot, int N) {
    extern __shared__ __half sm[];
    __half* Xs = sm;
    __half* Wsm = sm + TILE_M * XPAD;
    const int tid = threadIdx.x;
    const int nb = blockIdx.x * TILE_M;

    fill_w(Wsm, wslot, tid);
    fill_x(Xs, xsel ? g_x1h : g_h0h, nb, N, tid);
    __syncthreads();

    const int wid = tid >> 5, lane = tid & 31;
    const int m0 = (wid & 3) * 16, nbase = (wid >> 2) * 64;
    const int g = lane >> 2, tig = lane & 3;
    float c[8][4] = {};
    warp_mma(Xs, Wsm, m0, nbase, lane, c);

    int r0 = nb + m0 + g, r1 = r0 + 8;
#pragma unroll
    for (int nt = 0; nt < 8; nt++) {
        int col = nbase + nt * 8 + tig * 2;
        if (r0 < N) *(float2*)(g_partial + (size_t)r0 * H + col) = make_float2(c[nt][0], c[nt][1]);
        if (r1 < N) *(float2*)(g_partial + (size_t)r1 * H + col) = make_float2(c[nt][2], c[nt][3]);
    }
}

// ---------------------------------------------------------------------------
// sageB: (g_aggh @ Wn^T) + g_partial + biases [+relu] *exist
// out==nullptr: layer 1 -> write g_x1h (fp16). else: write fp32 out.
// ---------------------------------------------------------------------------
__global__ void __launch_bounds__(NTG)
sageB(int wslot,
      const float* __restrict__ bs,
      const float* __restrict__ bn,
      const float* __restrict__ exist,
      float* out, int N, int do_relu) {
    extern __shared__ __half sm[];
    __half* Xs = sm;
    __half* Wsm = sm + TILE_M * XPAD;
    const int tid = threadIdx.x;
    const int nb = blockIdx.x * TILE_M;

    fill_w(Wsm, wslot, tid);
    fill_x(Xs, g_aggh, nb, N, tid);
    __syncthreads();

    const int wid = tid >> 5, lane = tid & 31;
    const int m0 = (wid & 3) * 16, nbase = (wid >> 2) * 64;
    const int g = lane >> 2, tig = lane & 3;
    float c[8][4] = {};
    warp_mma(Xs, Wsm, m0, nbase, lane, c);

    int r0 = nb + m0 + g, r1 = r0 + 8;
    float e0 = (r0 < N) ? exist[r0] : 0.f;
    float e1 = (r1 < N) ? exist[r1] : 0.f;
#pragma unroll
    for (int nt = 0; nt < 8; nt++) {
        int col = nbase + nt * 8 + tig * 2;
        float bb0 = bs[col] + bn[col];
        float bb1 = bs[col + 1] + bn[col + 1];
        if (r0 < N) {
            float2 p = *(const float2*)(g_partial + (size_t)r0 * H + col);
            float v0 = c[nt][0] + p.x + bb0;
            float v1 = c[nt][1] + p.y + bb1;
            if (do_relu) { v0 = fmaxf(v0, 0.f); v1 = fmaxf(v1, 0.f); }
            v0 *= e0; v1 *= e1 * 0.f + e0;  // both cols same row -> e0
            if (out) {
                *(float2*)(out + (size_t)r0 * H + col) = make_float2(v0, v1);
            } else {
                __half2 hv = __float22half2_rn(make_float2(v0, v1));
                *(unsigned*)(g_x1h + (size_t)r0 * H + col) = *(unsigned*)&hv;
            }
        }
        if (r1 < N) {
            float2 p = *(const float2*)(g_partial + (size_t)r1 * H + col);
            float v0 = c[nt][2] + p.x + bb0;
            float v1 = c[nt][3] + p.y + bb1;
            if (do_relu) { v0 = fmaxf(v0, 0.f); v1 = fmaxf(v1, 0.f); }
            v0 *= e1; v1 *= e1;
            if (out) {
                *(float2*)(out + (size_t)r1 * H + col) = make_float2(v0, v1);
            } else {
                __half2 hv = __float22half2_rn(make_float2(v0, v1));
                *(unsigned*)(g_x1h + (size_t)r1 * H + col) = *(unsigned*)&hv;
            }
        }
    }
}

// ---------------------------------------------------------------------------
extern "C" void kernel_launch(void* const* d_in, const int* in_sizes, int n_in,
                              void* d_out, int out_size) {
    const float* attr  = (const float*)d_in[0];
    const float* cc    = (const float*)d_in[1];
    const float* bl    = (const float*)d_in[2];
    const float* exist = (const float*)d_in[3];
    const float* W_in  = (const float*)d_in[4];
    const float* b_in  = (const float*)d_in[5];
    const float* W1s   = (const float*)d_in[6];
    const float* b1s   = (const float*)d_in[7];
    const float* W1n   = (const float*)d_in[8];
    const float* b1n   = (const float*)d_in[9];
    const float* W2s   = (const float*)d_in[10];
    const float* b2s   = (const float*)d_in[11];
    const float* W2n   = (const float*)d_in[12];
    const float* b2n   = (const float*)d_in[13];
    const int*   ei    = (const int*)d_in[14];   // int32 (JAX x64 disabled)

    const int N    = in_sizes[3];
    const int ATTR = in_sizes[0] / N;
    const int E    = in_sizes[14] / 2;
    float* out = (float*)d_out;

    static cudaStream_t s1 = nullptr;
    static cudaEvent_t evT, evCSR, evIn, evS1, evX1, evS2;
    if (!s1) {
        cudaStreamCreateWithFlags(&s1, cudaStreamNonBlocking);
        cudaEventCreateWithFlags(&evT,   cudaEventDisableTiming);
        cudaEventCreateWithFlags(&evCSR, cudaEventDisableTiming);
        cudaEventCreateWithFlags(&evIn,  cudaEventDisableTiming);
        cudaEventCreateWithFlags(&evS1,  cudaEventDisableTiming);
        cudaEventCreateWithFlags(&evX1,  cudaEventDisableTiming);
        cudaEventCreateWithFlags(&evS2,  cudaEventDisableTiming);
    }

    const int SMEM = (TILE_M + 128) * XPAD * (int)sizeof(__half);  // ~52KB
    cudaFuncSetAttribute(input_gemm, cudaFuncAttributeMaxDynamicSharedMemorySize, SMEM);
    cudaFuncSetAttribute(self_gemm,  cudaFuncAttributeMaxDynamicSharedMemorySize, SMEM);
    cudaFuncSetAttribute(sageB,      cudaFuncAttributeMaxDynamicSharedMemorySize, SMEM);

    const int G = (N + TILE_M - 1) / TILE_M;
    const int edge_grid = (E + NT - 1) / NT;
    const int scan_grid = (N + SCAN_BLK - 1) / SCAN_BLK;
    const long long ga_threads = (long long)N * 32;
    const int ga_grid = (int)((ga_threads + NT - 1) / NT);
    cudaStream_t ms = (cudaStream_t)0;

    // main: weight fp16 conversion + zero g_cnt
    dim3 pr_grid((HH + NT - 1) / NT, 5);
    prep_weights<<<pr_grid, NT, 0, ms>>>(W_in, W1s, W1n, W2s, W2n, N);
    cudaEventRecord(evT, ms);

    // s1: CSR build chain
    cudaStreamWaitEvent(s1, evT, 0);
    deg_hist<<<edge_grid, NT, 0, s1>>>(ei, E);
    scanA<<<scan_grid, SCAN_BLK, 0, s1>>>(N);
    scanC<<<scan_grid, SCAN_BLK, 0, s1>>>(N, E, scan_grid);
    csr_fill<<<edge_grid, NT, 0, s1>>>(ei, E);
    cudaEventRecord(evCSR, s1);

    // main: input GEMM overlaps CSR build
    input_gemm<<<G, NTG, SMEM, ms>>>(attr, ATTR, cc, bl, exist, b_in, N);
    cudaEventRecord(evIn, ms);

    // ----- layer 1: self-GEMM (s1) || gather (main) -----
    cudaStreamWaitEvent(s1, evIn, 0);
    self_gemm<<<G, NTG, SMEM, s1>>>(0, 1, N);
    cudaEventRecord(evS1, s1);

    cudaStreamWaitEvent(ms, evCSR, 0);
    gather_agg_h<<<ga_grid, NT, 0, ms>>>(0, N);
    cudaStreamWaitEvent(ms, evS1, 0);
    sageB<<<G, NTG, SMEM, ms>>>(2, b1s, b1n, exist, nullptr, N, 1);
    cudaEventRecord(evX1, ms);

    // ----- layer 2: self-GEMM (s1) || gather (main) -----
    cudaStreamWaitEvent(s1, evX1, 0);
    self_gemm<<<G, NTG, SMEM, s1>>>(1, 3, N);
    cudaEventRecord(evS2, s1);

    gather_agg_h<<<ga_grid, NT, 0, ms>>>(1, N);
    cudaStreamWaitEvent(ms, evS2, 0);
    sageB<<<G, NTG, SMEM, ms>>>(4, b2s, b2n, exist, out, N, 0);
}